// round 14
// baseline (speedup 1.0000x reference)
#include <cuda_runtime.h>
#include <cuda_fp16.h>
#include <cuda_bf16.h>
#include <mma.h>
#include <math.h>
#include <stdint.h>

using namespace nvcuda;

// Problem constants
#define BB   2
#define SS   2048
#define HID  1024
#define NH   16
#define NKV  4
#define MM   (BB*SS)          // 4096 rows
#define KVD  256
#define NQKV 1536             // fused projection width: 1024 q + 256 k + 256 v
#define RMS_EPS 1.1920929e-07f

// ---------------- scratch (device globals; no allocation allowed) ----------
__device__ __half g_xh[MM*HID];          // fp16 hidden
__device__ __half g_wqkvh[HID*NQKV];     // fp16 [Wq | Wk | Wv], [1024][1536]
__device__ __half g_woh[HID*HID];
__device__ float  g_b2qkv[16*NQKV];      // bias broadcast rows (16 identical)
__device__ float  g_b2o[16*HID];
__device__ float  g_qkv[(size_t)MM*NQKV];// fused projection out fp32 [M][1536]
__device__ __half g_qnh[MM*HID];         // roped+normed q fp16, [B][H][S][64]
__device__ __half g_knh[MM*KVD];         // roped+normed k fp16, [B][HKV][S][64]
__device__ __half g_vth[MM*KVD];         // V transposed fp16, [B][HKV][64][S]
__device__ __half g_ctxh[MM*HID];        // attention context fp16, [B][S][H*64]
__device__ __nv_bfloat16 g_maskb[(size_t)BB*SS*SS];  // (mask - 8) in bf16

// bit-cast helper
__device__ __forceinline__ unsigned h2_as_u32(__half2 h) {
    union { __half2 h2; unsigned u; } cv; cv.h2 = h; return cv.u;
}

// fp16 mma m16n8k16, fp32 accumulate
__device__ __forceinline__ void mma_f16(float d[4], const unsigned a[4],
                                        unsigned b0, unsigned b1) {
    asm volatile(
        "mma.sync.aligned.m16n8k16.row.col.f32.f16.f16.f32 "
        "{%0,%1,%2,%3}, {%4,%5,%6,%7}, {%8,%9}, {%0,%1,%2,%3};\n"
        : "+f"(d[0]), "+f"(d[1]), "+f"(d[2]), "+f"(d[3])
        : "r"(a[0]), "r"(a[1]), "r"(a[2]), "r"(a[3]), "r"(b0), "r"(b1));
}

// ldmatrix x4 (4 m8n8 b16 tiles)
__device__ __forceinline__ void ldsm4(unsigned& r0, unsigned& r1,
                                      unsigned& r2, unsigned& r3, uint32_t addr) {
    asm volatile("ldmatrix.sync.aligned.m8n8.x4.shared.b16 {%0,%1,%2,%3}, [%4];\n"
                 : "=r"(r0), "=r"(r1), "=r"(r2), "=r"(r3) : "r"(addr));
}

// cp.async 16B
__device__ __forceinline__ void cp16(uint32_t dst, const void* src) {
    asm volatile("cp.async.cg.shared.global [%0], [%1], 16;\n"
                 :: "r"(dst), "l"(src));
}
__device__ __forceinline__ void cp_commit() {
    asm volatile("cp.async.commit_group;\n" ::: "memory");
}
__device__ __forceinline__ void cp_wait0() {
    asm volatile("cp.async.wait_group 0;\n" ::: "memory");
}

// ============================================================================
// Single fused prep kernel (grid-strided segments)
// ============================================================================
#define PN0 (MM*HID)          // 4194304
#define PN1 (HID*NQKV)        // 1572864
#define PN2 (HID*HID)         // 1048576
#define PN3 (16*NQKV + 16*HID)// 40960
#define PN4 (BB*SS*SS)        // 8388608
#define POFF1 PN0
#define POFF2 (POFF1+PN1)
#define POFF3 (POFF2+PN2)
#define POFF4 (POFF3+PN3)
#define PTOT  (POFF4+PN4)

__global__ void prep(const float* __restrict__ x,    const float* __restrict__ mask,
                     const float* __restrict__ Wq,   const float* __restrict__ bq,
                     const float* __restrict__ Wk,   const float* __restrict__ bk,
                     const float* __restrict__ Wv,   const float* __restrict__ bv,
                     const float* __restrict__ Wo,   const float* __restrict__ bo) {
    int i = (blockIdx.x * blockDim.x + threadIdx.x) * 4;
    if (i < POFF1) {                     // x -> fp16
        float4 v = *(const float4*)&x[i];
        *(__half2*)&g_xh[i]     = __floats2half2_rn(v.x, v.y);
        *(__half2*)&g_xh[i + 2] = __floats2half2_rn(v.z, v.w);
    } else if (i < POFF2) {              // wqkv concat -> fp16
        int j = i - POFF1;
        int row = j / NQKV, col = j % NQKV;
        const float* src;
        if (col < 1024)      src = Wq + (size_t)row * 1024 + col;
        else if (col < 1280) src = Wk + (size_t)row * 256 + (col - 1024);
        else                 src = Wv + (size_t)row * 256 + (col - 1280);
        float4 v = *(const float4*)src;
        *(__half2*)&g_wqkvh[j]     = __floats2half2_rn(v.x, v.y);
        *(__half2*)&g_wqkvh[j + 2] = __floats2half2_rn(v.z, v.w);
    } else if (i < POFF3) {              // Wo -> fp16
        int j = i - POFF2;
        float4 v = *(const float4*)&Wo[j];
        *(__half2*)&g_woh[j]     = __floats2half2_rn(v.x, v.y);
        *(__half2*)&g_woh[j + 2] = __floats2half2_rn(v.z, v.w);
    } else if (i < POFF4) {              // bias broadcast
        int j = i - POFF3;
        if (j < 16 * NQKV) {
            int c = j % NQKV;
            float4 v = c < 1024 ? *(const float4*)&bq[c]
                     : (c < 1280 ? *(const float4*)&bk[c - 1024]
                                 : *(const float4*)&bv[c - 1280]);
            *(float4*)&g_b2qkv[j] = v;
        } else {
            int j2 = j - 16 * NQKV;
            *(float4*)&g_b2o[j2] = *(const float4*)&bo[j2 % HID];
        }
    } else if (i < PTOT) {               // mask -> bf16 (minus 8)
        int j = i - POFF4;
        float4 v = *(const float4*)&mask[j];
        *(__nv_bfloat162*)&g_maskb[j]     = __floats2bfloat162_rn(v.x - 8.0f, v.y - 8.0f);
        *(__nv_bfloat162*)&g_maskb[j + 2] = __floats2bfloat162_rn(v.z - 8.0f, v.w - 8.0f);
    }
}

// ============================================================================
// fp16 wmma GEMM: C[M,N] = A[M,K] @ W[K,N] + bias (acc init from bias2d rows).
// Block 128x128, 8 warps (4 row-bands x 2 col-bands), warp 32x64, k-step 64.
// 2-stage cp.async pipeline (dynamic smem); fragments stored to global fp32.
// ============================================================================
#define HA_LD 72       // As stride in halves (144B rows, 16B-aligned)
#define HB_LD 136      // Bs stride in halves (272B rows, 16B-aligned)
#define STG_H 17920    // halves per stage = 128*72 + 64*136
#define GSMEM (2*STG_H*2)   // 71680 bytes

__global__ __launch_bounds__(256, 2) void gemm_h(
        const __half* __restrict__ A, const __half* __restrict__ W,
        const float* __restrict__ bias2d, float* __restrict__ C,
        int M, int N, int K) {
    extern __shared__ __half buf[];
    const uint32_t s_u32 = (uint32_t)__cvta_generic_to_shared(buf);

    const int tid  = threadIdx.x;
    const int warp = tid >> 5;
    const int wm   = warp & 3;                // row band (32 rows)
    const int wn   = warp >> 2;               // col band (64 cols)
    const int m0   = blockIdx.y * 128;
    const int n0   = blockIdx.x * 128;

    auto issue = [&](int k0, int s) {
        const uint32_t base = s_u32 + (uint32_t)s * STG_H * 2;
        #pragma unroll
        for (int i = 0; i < 4; i++) {               // A: 1024 x 16B (128r x 8g)
            int v = tid + i * 256;
            int r = v >> 3, o = v & 7;
            cp16(base + (r * HA_LD + o * 8) * 2,
                 &A[(size_t)(m0 + r) * K + k0 + o * 8]);
        }
        #pragma unroll
        for (int i = 0; i < 4; i++) {               // B: 1024 x 16B (64r x 16g)
            int v = tid + i * 256;
            int r = v >> 4, o = v & 15;
            cp16(base + (128 * HA_LD + r * HB_LD + o * 8) * 2,
                 &W[(size_t)(k0 + r) * N + n0 + o * 8]);
        }
        cp_commit();
    };

    wmma::fragment<wmma::accumulator, 16, 16, 16, float> acc[2][4];
    #pragma unroll
    for (int i = 0; i < 2; i++)
        #pragma unroll
        for (int j = 0; j < 4; j++)
            wmma::load_matrix_sync(acc[i][j], bias2d + n0 + wn * 64 + j * 16,
                                   N, wmma::mem_row_major);

    issue(0, 0);
    int s = 0;
    for (int k0 = 0; k0 < K; k0 += 64) {
        cp_wait0();
        __syncthreads();           // data visible + prev stage fully consumed
        if (k0 + 64 < K) issue(k0 + 64, s ^ 1);

        const __half* As = buf + (size_t)s * STG_H;
        const __half* Bs = As + 128 * HA_LD;
        #pragma unroll
        for (int kk = 0; kk < 64; kk += 16) {
            wmma::fragment<wmma::matrix_a, 16, 16, 16, __half, wmma::row_major> a[2];
            wmma::fragment<wmma::matrix_b, 16, 16, 16, __half, wmma::row_major> b[4];
            #pragma unroll
            for (int i = 0; i < 2; i++)
                wmma::load_matrix_sync(a[i], As + (wm * 32 + i * 16) * HA_LD + kk, HA_LD);
            #pragma unroll
            for (int j = 0; j < 4; j++)
                wmma::load_matrix_sync(b[j], Bs + kk * HB_LD + wn * 64 + j * 16, HB_LD);
            #pragma unroll
            for (int i = 0; i < 2; i++)
                #pragma unroll
                for (int j = 0; j < 4; j++)
                    wmma::mma_sync(acc[i][j], a[i], b[j], acc[i][j]);
        }
        s ^= 1;
    }

    // direct fragment store to global fp32
    #pragma unroll
    for (int i = 0; i < 2; i++)
        #pragma unroll
        for (int j = 0; j < 4; j++)
            wmma::store_matrix_sync(&C[(size_t)(m0 + wm * 32 + i * 16) * N + n0 + wn * 64 + j * 16],
                                    acc[i][j], N, wmma::mem_row_major);
}

// ------------- RoPE + per-head RMSNorm for Q -> fp16 [B][H][S][64] ---------
__global__ void rope_norm_q() {
    const int spos = blockIdx.x;
    __shared__ float r2[1024];
    const int t = threadIdx.x;             // 512 threads
    const float inv = powf(10000.0f, -(float)t / 512.0f);
    float sn, cs; sincosf((float)spos * inv, &sn, &cs);
    const int w = t >> 5, lane = t & 31;
    #pragma unroll
    for (int b = 0; b < BB; b++) {
        const size_t row = (size_t)(b * SS + spos) * NQKV;
        const float x1 = g_qkv[row + t];
        const float x2 = g_qkv[row + t + 512];
        r2[t]       = x1 * cs - x2 * sn;
        r2[t + 512] = x2 * cs + x1 * sn;
        __syncthreads();
        const float v0 = r2[w * 64 + lane];
        const float v1 = r2[w * 64 + 32 + lane];
        float ss = v0 * v0 + v1 * v1;
        #pragma unroll
        for (int o = 16; o; o >>= 1) ss += __shfl_xor_sync(0xffffffffu, ss, o);
        const float rms = rsqrtf(ss * (1.0f / 64.0f) + RMS_EPS);
        const size_t base = ((size_t)(b * NH + w) * SS + spos) * 64;
        g_qnh[base + lane]      = __float2half(v0 * rms);
        g_qnh[base + 32 + lane] = __float2half(v1 * rms);
        __syncthreads();
    }
}

// ------------- RoPE + per-head RMSNorm for K -> fp16 [B][HKV][S][64] -------
__global__ void rope_norm_k() {
    const int spos = blockIdx.x;
    __shared__ float r2[256];
    const int t = threadIdx.x;             // 128 threads
    const float inv = powf(10000.0f, -(float)t / 128.0f);
    float sn, cs; sincosf((float)spos * inv, &sn, &cs);
    const int w = t >> 5, lane = t & 31;
    #pragma unroll
    for (int b = 0; b < BB; b++) {
        const size_t row = (size_t)(b * SS + spos) * NQKV + 1024;
        const float x1 = g_qkv[row + t];
        const float x2 = g_qkv[row + t + 128];
        r2[t]       = x1 * cs - x2 * sn;
        r2[t + 128] = x2 * cs + x1 * sn;
        __syncthreads();
        const float v0 = r2[w * 64 + lane];
        const float v1 = r2[w * 64 + 32 + lane];
        float ss = v0 * v0 + v1 * v1;
        #pragma unroll
        for (int o = 16; o; o >>= 1) ss += __shfl_xor_sync(0xffffffffu, ss, o);
        const float rms = rsqrtf(ss * (1.0f / 64.0f) + RMS_EPS);
        const size_t base = ((size_t)(b * NKV + w) * SS + spos) * 64;
        g_knh[base + lane]      = __float2half(v0 * rms);
        g_knh[base + 32 + lane] = __float2half(v1 * rms);
        __syncthreads();
    }
}

// ------------- V transpose: g_qkv v-cols -> g_vth [B][kvh][64][S] ----------
__global__ void transpose_v() {
    const int s0  = blockIdx.x * 128;
    const int bk  = blockIdx.y;
    const int b   = bk >> 2, kvh = bk & 3;
    __shared__ float tile[128][65];
    const int t = threadIdx.x;
    #pragma unroll
    for (int i = 0; i < 8; i++) {
        int v = t + i * 256;
        int r = v >> 4, o = v & 15;
        float4 val = *(const float4*)
            &g_qkv[(size_t)(b * SS + s0 + r) * NQKV + 1280 + kvh * 64 + o * 4];
        tile[r][o * 4 + 0] = val.x;
        tile[r][o * 4 + 1] = val.y;
        tile[r][o * 4 + 2] = val.z;
        tile[r][o * 4 + 3] = val.w;
    }
    __syncthreads();
    const int w = t >> 5, lane = t & 31;
    #pragma unroll
    for (int i = 0; i < 8; i++) {
        int d = w * 8 + i;
        size_t orow = ((size_t)(b * NKV + kvh) * 64 + d) * SS + s0;
        float a0 = tile[lane * 4 + 0][d];
        float a1 = tile[lane * 4 + 1][d];
        float a2 = tile[lane * 4 + 2][d];
        float a3 = tile[lane * 4 + 3][d];
        *(__half2*)&g_vth[orow + lane * 4]     = __floats2half2_rn(a0, a1);
        *(__half2*)&g_vth[orow + lane * 4 + 2] = __floats2half2_rn(a2, a3);
    }
}

// ============================================================================
// flash attention, fp16 mma + ldmatrix + cp.async, FIXED softmax max (=8).
// ============================================================================
#define KLD 72   // smem stride in halves (144B rows, 16B-aligned)

__global__ __launch_bounds__(256, 2) void flash_attn_h16(const __nv_bfloat16* __restrict__ maskb) {
    const int q0  = blockIdx.x * 128;
    const int bh  = blockIdx.y;            // b*16 + h
    const int b   = bh >> 4, h = bh & 15;
    const int kvh = h >> 2;
    __shared__ alignas(16) __half Ks[2][64 * KLD];
    __shared__ alignas(16) __half Vs[2][64 * KLD];

    const int tid  = threadIdx.x;
    const int warp = tid >> 5, lane = tid & 31;
    const int g = lane >> 2, c = lane & 3;

    const uint32_t ksu = (uint32_t)__cvta_generic_to_shared(&Ks[0][0]);
    const uint32_t vsu = (uint32_t)__cvta_generic_to_shared(&Vs[0][0]);
    const int tile = lane >> 3, rr = lane & 7;
    const int off_ld = ((tile >> 1) * 8 + rr) * KLD + (tile & 1) * 8;

    const int qrow0 = q0 + warp * 16 + g;   // lane's rows: qrow0, qrow0+8

    unsigned QF[4][4];
    {
        const __half* q0p = g_qnh + ((size_t)(b * NH + h) * SS + qrow0) * 64;
        const __half* q1p = q0p + 8 * 64;
        #pragma unroll
        for (int kf = 0; kf < 4; kf++) {
            QF[kf][0] = *(const unsigned*)&q0p[kf * 16 + 2 * c];
            QF[kf][1] = *(const unsigned*)&q1p[kf * 16 + 2 * c];
            QF[kf][2] = *(const unsigned*)&q0p[kf * 16 + 2 * c + 8];
            QF[kf][3] = *(const unsigned*)&q1p[kf * 16 + 2 * c + 8];
        }
    }

    float O[8][4];
    #pragma unroll
    for (int nf = 0; nf < 8; nf++) { O[nf][0] = O[nf][1] = O[nf][2] = O[nf][3] = 0.f; }
    float l0 = 0.f, l1 = 0.f;

    const size_t kvbase = (size_t)(b * NKV + kvh) * SS * 64;
    const __nv_bfloat16* mrow0 = maskb + ((size_t)b * SS + qrow0) * SS;
    const __nv_bfloat16* mrow1 = mrow0 + (size_t)8 * SS;

    auto issue_tile = [&](int k0, int s) {
        const uint32_t kb = ksu + (uint32_t)s * 64 * KLD * 2;
        const uint32_t vb = vsu + (uint32_t)s * 64 * KLD * 2;
        #pragma unroll
        for (int i = 0; i < 2; i++) {
            int v = tid + i * 256;
            int r = v >> 3, o = v & 7;
            cp16(kb + (r * KLD + o * 8) * 2,
                 &g_knh[kvbase + (size_t)(k0 + r) * 64 + o * 8]);
            cp16(vb + (r * KLD + o * 8) * 2,
                 &g_vth[kvbase + (size_t)r * SS + k0 + o * 8]);
        }
        cp_commit();
    };

    issue_tile(0, 0);
    int s = 0;
    for (int k0 = 0; k0 < SS; k0 += 64) {
        cp_wait0();
        __syncthreads();
        if (k0 + 64 < SS) issue_tile(k0 + 64, s ^ 1);

        const uint32_t ksb = ksu + (uint32_t)s * 64 * KLD * 2;
        const uint32_t vsb = vsu + (uint32_t)s * 64 * KLD * 2;

        // prefetch mask for this tile (overlaps with QK^T mma below)
        float2 MK0[8], MK1[8];
        #pragma unroll
        for (int nf = 0; nf < 8; nf++) {
            MK0[nf] = __bfloat1622float2(*(const __nv_bfloat162*)&mrow0[k0 + nf * 8 + 2 * c]);
            MK1[nf] = __bfloat1622float2(*(const __nv_bfloat162*)&mrow1[k0 + nf * 8 + 2 * c]);
        }

        float S[8][4];
        #pragma unroll
        for (int nf = 0; nf < 8; nf++) S[nf][0] = S[nf][1] = S[nf][2] = S[nf][3] = 0.f;
        #pragma unroll
        for (int kf = 0; kf < 4; kf++) {
            #pragma unroll
            for (int nfp = 0; nfp < 4; nfp++) {
                unsigned b0a, b1a, b0b, b1b;
                ldsm4(b0a, b1a, b0b, b1b,
                      ksb + (uint32_t)(off_ld + nfp * 16 * KLD + kf * 16) * 2);
                mma_f16(S[2 * nfp],     QF[kf], b0a, b1a);
                mma_f16(S[2 * nfp + 1], QF[kf], b0b, b1b);
            }
        }

        unsigned PA[4][4];
        #pragma unroll
        for (int nf = 0; nf < 8; nf++) {
            float p0 = __expf(fmaf(S[nf][0], 0.125f, MK0[nf].x));
            float p1 = __expf(fmaf(S[nf][1], 0.125f, MK0[nf].y));
            float p2 = __expf(fmaf(S[nf][2], 0.125f, MK1[nf].x));
            float p3 = __expf(fmaf(S[nf][3], 0.125f, MK1[nf].y));
            l0 += p0 + p1; l1 += p2 + p3;
            const int kf = nf >> 1, hi = nf & 1;
            PA[kf][0 + 2 * hi] = h2_as_u32(__floats2half2_rn(p0, p1));
            PA[kf][1 + 2 * hi] = h2_as_u32(__floats2half2_rn(p2, p3));
        }

        #pragma unroll
        for (int kf = 0; kf < 4; kf++) {
            #pragma unroll
            for (int nfp = 0; nfp < 4; nfp++) {
                unsigned b0a, b1a, b0b, b1b;
                ldsm4(b0a, b1a, b0b, b1b,
                      vsb + (uint32_t)(off_ld + nfp * 16 * KLD + kf * 16) * 2);
                mma_f16(O[2 * nfp],     PA[kf], b0a, b1a);
                mma_f16(O[2 * nfp + 1], PA[kf], b0b, b1b);
            }
        }
        s ^= 1;
    }

    l0 += __shfl_xor_sync(0xffffffffu, l0, 1);
    l0 += __shfl_xor_sync(0xffffffffu, l0, 2);
    l1 += __shfl_xor_sync(0xffffffffu, l1, 1);
    l1 += __shfl_xor_sync(0xffffffffu, l1, 2);
    const float inv0 = 1.0f / l0, inv1 = 1.0f / l1;
    const size_t ob0 = ((size_t)b * SS + qrow0) * HID + (size_t)h * 64;
    const size_t ob1 = ob0 + (size_t)8 * HID;
    #pragma unroll
    for (int nf = 0; nf < 8; nf++) {
        *(__half2*)&g_ctxh[ob0 + nf * 8 + 2 * c] =
            __floats2half2_rn(O[nf][0] * inv0, O[nf][1] * inv0);
        *(__half2*)&g_ctxh[ob1 + nf * 8 + 2 * c] =
            __floats2half2_rn(O[nf][2] * inv1, O[nf][3] * inv1);
    }
}

// ---------------------------------------------------------------------------
extern "C" void kernel_launch(void* const* d_in, const int* in_sizes, int n_in,
                              void* d_out, int out_size) {
    const float* x    = (const float*)d_in[0];
    const float* mask = (const float*)d_in[1];
    const float* Wq   = (const float*)d_in[2];
    const float* bq   = (const float*)d_in[3];
    const float* Wk   = (const float*)d_in[4];
    const float* bk   = (const float*)d_in[5];
    const float* Wv   = (const float*)d_in[6];
    const float* bv   = (const float*)d_in[7];
    const float* Wo   = (const float*)d_in[8];
    const float* bo   = (const float*)d_in[9];
    float* out = (float*)d_out;

    __half *p_xh, *p_wqkvh, *p_woh, *p_ctxh;
    float *p_qkv, *p_b2qkv, *p_b2o;
    __nv_bfloat16* p_maskb;
    cudaGetSymbolAddress((void**)&p_xh,     g_xh);
    cudaGetSymbolAddress((void**)&p_wqkvh,  g_wqkvh);
    cudaGetSymbolAddress((void**)&p_woh,    g_woh);
    cudaGetSymbolAddress((void**)&p_ctxh,   g_ctxh);
    cudaGetSymbolAddress((void**)&p_qkv,    g_qkv);
    cudaGetSymbolAddress((void**)&p_b2qkv,  g_b2qkv);
    cudaGetSymbolAddress((void**)&p_b2o,    g_b2o);
    cudaGetSymbolAddress((void**)&p_maskb,  g_maskb);

    cudaFuncSetAttribute(gemm_h, cudaFuncAttributeMaxDynamicSharedMemorySize, GSMEM);

    // 0) single fused prep (all conversions + bias broadcast)
    prep<<<(PTOT / 4 + 255) / 256, 256>>>(x, mask, Wq, bq, Wk, bk, Wv, bv, Wo, bo);

    // 1) fused QKV projection (fp16 tensor cores, fp32 accumulate)
    gemm_h<<<dim3(NQKV / 128, MM / 128), 256, GSMEM>>>(p_xh, p_wqkvh, p_b2qkv, p_qkv,
                                                       MM, NQKV, HID);

    // 2) rope + rmsnorm + relayout (fp16 outputs), V transpose
    rope_norm_q<<<SS, 512>>>();
    rope_norm_k<<<SS, 128>>>();
    transpose_v<<<dim3(SS / 128, BB * NKV), 256>>>();

    // 3) attention (register flash, fixed-max softmax)
    flash_attn_h16<<<dim3(SS / 128, BB * NH), 256>>>(p_maskb);

    // 4) output projection straight into d_out
    gemm_h<<<dim3(HID / 128, MM / 128), 256, GSMEM>>>(p_ctxh, p_woh, p_b2o, out,
                                                      MM, HID, HID);
}

// round 15
// speedup vs baseline: 1.4722x; 1.4722x over previous
#include <cuda_runtime.h>
#include <cuda_fp16.h>
#include <cuda_bf16.h>
#include <mma.h>
#include <math.h>
#include <stdint.h>

using namespace nvcuda;

// Problem constants
#define BB   2
#define SS   2048
#define HID  1024
#define NH   16
#define NKV  4
#define MM   (BB*SS)          // 4096 rows
#define KVD  256
#define NQKV 1536             // fused projection width: 1024 q + 256 k + 256 v
#define RMS_EPS 1.1920929e-07f

// ---------------- scratch (device globals; no allocation allowed) ----------
__device__ __half g_xh[MM*HID];          // fp16 hidden
__device__ __half g_wqkvh[HID*NQKV];     // fp16 [Wq | Wk | Wv], [1024][1536]
__device__ __half g_woh[HID*HID];
__device__ float  g_b2qkv[16*NQKV];      // bias broadcast rows (16 identical)
__device__ float  g_b2o[16*HID];
__device__ float  g_qkv[(size_t)MM*NQKV];// fused projection out fp32 [M][1536]
__device__ __half g_qnh[MM*HID];         // roped+normed q fp16, [B][H][S][64]
__device__ __half g_knh[MM*KVD];         // roped+normed k fp16, [B][HKV][S][64]
__device__ __half g_vth[MM*KVD];         // V transposed fp16, [B][HKV][64][S]
__device__ __half g_ctxh[MM*HID];        // attention context fp16, [B][S][H*64]
__device__ __nv_bfloat16 g_maskb[(size_t)BB*SS*SS];  // (mask - 8) in bf16

// bit-cast helper
__device__ __forceinline__ unsigned h2_as_u32(__half2 h) {
    union { __half2 h2; unsigned u; } cv; cv.h2 = h; return cv.u;
}

// fp16 mma m16n8k16, fp32 accumulate
__device__ __forceinline__ void mma_f16(float d[4], const unsigned a[4],
                                        unsigned b0, unsigned b1) {
    asm volatile(
        "mma.sync.aligned.m16n8k16.row.col.f32.f16.f16.f32 "
        "{%0,%1,%2,%3}, {%4,%5,%6,%7}, {%8,%9}, {%0,%1,%2,%3};\n"
        : "+f"(d[0]), "+f"(d[1]), "+f"(d[2]), "+f"(d[3])
        : "r"(a[0]), "r"(a[1]), "r"(a[2]), "r"(a[3]), "r"(b0), "r"(b1));
}

// ldmatrix x4 (4 m8n8 b16 tiles)
__device__ __forceinline__ void ldsm4(unsigned& r0, unsigned& r1,
                                      unsigned& r2, unsigned& r3, uint32_t addr) {
    asm volatile("ldmatrix.sync.aligned.m8n8.x4.shared.b16 {%0,%1,%2,%3}, [%4];\n"
                 : "=r"(r0), "=r"(r1), "=r"(r2), "=r"(r3) : "r"(addr));
}

// cp.async 16B
__device__ __forceinline__ void cp16(uint32_t dst, const void* src) {
    asm volatile("cp.async.cg.shared.global [%0], [%1], 16;\n"
                 :: "r"(dst), "l"(src));
}
__device__ __forceinline__ void cp_commit() {
    asm volatile("cp.async.commit_group;\n" ::: "memory");
}
__device__ __forceinline__ void cp_wait0() {
    asm volatile("cp.async.wait_group 0;\n" ::: "memory");
}
__device__ __forceinline__ void cp_wait1() {
    asm volatile("cp.async.wait_group 1;\n" ::: "memory");
}

// ============================================================================
// Single fused prep kernel (grid-strided segments)
// ============================================================================
#define PN0 (MM*HID)          // 4194304
#define PN1 (HID*NQKV)        // 1572864
#define PN2 (HID*HID)         // 1048576
#define PN3 (16*NQKV + 16*HID)// 40960
#define PN4 (BB*SS*SS)        // 8388608
#define POFF1 PN0
#define POFF2 (POFF1+PN1)
#define POFF3 (POFF2+PN2)
#define POFF4 (POFF3+PN3)
#define PTOT  (POFF4+PN4)

__global__ void prep(const float* __restrict__ x,    const float* __restrict__ mask,
                     const float* __restrict__ Wq,   const float* __restrict__ bq,
                     const float* __restrict__ Wk,   const float* __restrict__ bk,
                     const float* __restrict__ Wv,   const float* __restrict__ bv,
                     const float* __restrict__ Wo,   const float* __restrict__ bo) {
    int i = (blockIdx.x * blockDim.x + threadIdx.x) * 4;
    if (i < POFF1) {                     // x -> fp16
        float4 v = *(const float4*)&x[i];
        *(__half2*)&g_xh[i]     = __floats2half2_rn(v.x, v.y);
        *(__half2*)&g_xh[i + 2] = __floats2half2_rn(v.z, v.w);
    } else if (i < POFF2) {              // wqkv concat -> fp16
        int j = i - POFF1;
        int row = j / NQKV, col = j % NQKV;
        const float* src;
        if (col < 1024)      src = Wq + (size_t)row * 1024 + col;
        else if (col < 1280) src = Wk + (size_t)row * 256 + (col - 1024);
        else                 src = Wv + (size_t)row * 256 + (col - 1280);
        float4 v = *(const float4*)src;
        *(__half2*)&g_wqkvh[j]     = __floats2half2_rn(v.x, v.y);
        *(__half2*)&g_wqkvh[j + 2] = __floats2half2_rn(v.z, v.w);
    } else if (i < POFF3) {              // Wo -> fp16
        int j = i - POFF2;
        float4 v = *(const float4*)&Wo[j];
        *(__half2*)&g_woh[j]     = __floats2half2_rn(v.x, v.y);
        *(__half2*)&g_woh[j + 2] = __floats2half2_rn(v.z, v.w);
    } else if (i < POFF4) {              // bias broadcast
        int j = i - POFF3;
        if (j < 16 * NQKV) {
            int c = j % NQKV;
            float4 v = c < 1024 ? *(const float4*)&bq[c]
                     : (c < 1280 ? *(const float4*)&bk[c - 1024]
                                 : *(const float4*)&bv[c - 1280]);
            *(float4*)&g_b2qkv[j] = v;
        } else {
            int j2 = j - 16 * NQKV;
            *(float4*)&g_b2o[j2] = *(const float4*)&bo[j2 % HID];
        }
    } else if (i < PTOT) {               // mask -> bf16 (minus 8)
        int j = i - POFF4;
        float4 v = *(const float4*)&mask[j];
        *(__nv_bfloat162*)&g_maskb[j]     = __floats2bfloat162_rn(v.x - 8.0f, v.y - 8.0f);
        *(__nv_bfloat162*)&g_maskb[j + 2] = __floats2bfloat162_rn(v.z - 8.0f, v.w - 8.0f);
    }
}

// ============================================================================
// fp16 wmma GEMM: C[M,N] = A[M,K] @ W[K,N] + bias (acc init from bias2d rows).
// Block 128x128, 8 warps (4 row-bands x 2 col-bands), warp 32x64, k-step 32.
// 3-stage cp.async pipeline (dynamic smem); fragments stored to global fp32.
// ============================================================================
#define HA_LD 40       // As stride in halves (80B rows, 16B-aligned)
#define HB_LD 136      // Bs stride in halves (272B rows, 16B-aligned)
#define STG_H 9472     // halves per stage = 128*40 + 32*136
#define GSMEM (3*STG_H*2)   // 56832 bytes (3 stages)

__global__ __launch_bounds__(256, 2) void gemm_h(
        const __half* __restrict__ A, const __half* __restrict__ W,
        const float* __restrict__ bias2d, float* __restrict__ C,
        int M, int N, int K) {
    extern __shared__ __half buf[];
    const uint32_t s_u32 = (uint32_t)__cvta_generic_to_shared(buf);

    const int tid  = threadIdx.x;
    const int warp = tid >> 5;
    const int wm   = warp & 3;                // row band (32 rows)
    const int wn   = warp >> 2;               // col band (64 cols)
    const int m0   = blockIdx.y * 128;
    const int n0   = blockIdx.x * 128;

    auto issue = [&](int k0, int s) {
        const uint32_t base = s_u32 + (uint32_t)s * STG_H * 2;
        #pragma unroll
        for (int i = 0; i < 2; i++) {               // A: 512 x 16B
            int v = tid + i * 256;
            int r = v >> 2, o = v & 3;
            cp16(base + (r * HA_LD + o * 8) * 2,
                 &A[(size_t)(m0 + r) * K + k0 + o * 8]);
        }
        #pragma unroll
        for (int i = 0; i < 2; i++) {               // B: 512 x 16B
            int v = tid + i * 256;
            int r = v >> 4, o = v & 15;
            cp16(base + (128 * HA_LD + r * HB_LD + o * 8) * 2,
                 &W[(size_t)(k0 + r) * N + n0 + o * 8]);
        }
        cp_commit();
    };

    wmma::fragment<wmma::accumulator, 16, 16, 16, float> acc[2][4];
    #pragma unroll
    for (int i = 0; i < 2; i++)
        #pragma unroll
        for (int j = 0; j < 4; j++)
            wmma::load_matrix_sync(acc[i][j], bias2d + n0 + wn * 64 + j * 16,
                                   N, wmma::mem_row_major);

    const int NIT = K >> 5;
    issue(0, 0);
    if (NIT > 1) issue(32, 1);
    int s = 0;
    for (int it = 0; it < NIT; it++) {
        if (it == NIT - 1) cp_wait0(); else cp_wait1();
        __syncthreads();           // stage s landed + stage (s+2)%3 fully consumed
        if (it + 2 < NIT) issue((it + 2) << 5, (s + 2) % 3);

        const __half* As = buf + (size_t)s * STG_H;
        const __half* Bs = As + 128 * HA_LD;
        #pragma unroll
        for (int kk = 0; kk < 32; kk += 16) {
            wmma::fragment<wmma::matrix_a, 16, 16, 16, __half, wmma::row_major> a[2];
            wmma::fragment<wmma::matrix_b, 16, 16, 16, __half, wmma::row_major> b[4];
            #pragma unroll
            for (int i = 0; i < 2; i++)
                wmma::load_matrix_sync(a[i], As + (wm * 32 + i * 16) * HA_LD + kk, HA_LD);
            #pragma unroll
            for (int j = 0; j < 4; j++)
                wmma::load_matrix_sync(b[j], Bs + kk * HB_LD + wn * 64 + j * 16, HB_LD);
            #pragma unroll
            for (int i = 0; i < 2; i++)
                #pragma unroll
                for (int j = 0; j < 4; j++)
                    wmma::mma_sync(acc[i][j], a[i], b[j], acc[i][j]);
        }
        s = (s + 1) % 3;
    }

    // direct fragment store to global fp32
    #pragma unroll
    for (int i = 0; i < 2; i++)
        #pragma unroll
        for (int j = 0; j < 4; j++)
            wmma::store_matrix_sync(&C[(size_t)(m0 + wm * 32 + i * 16) * N + n0 + wn * 64 + j * 16],
                                    acc[i][j], N, wmma::mem_row_major);
}

// ------------- RoPE + per-head RMSNorm for Q -> fp16 [B][H][S][64] ---------
__global__ void rope_norm_q() {
    const int spos = blockIdx.x;
    __shared__ float r2[1024];
    const int t = threadIdx.x;             // 512 threads
    const float inv = powf(10000.0f, -(float)t / 512.0f);
    float sn, cs; sincosf((float)spos * inv, &sn, &cs);
    const int w = t >> 5, lane = t & 31;
    #pragma unroll
    for (int b = 0; b < BB; b++) {
        const size_t row = (size_t)(b * SS + spos) * NQKV;
        const float x1 = g_qkv[row + t];
        const float x2 = g_qkv[row + t + 512];
        r2[t]       = x1 * cs - x2 * sn;
        r2[t + 512] = x2 * cs + x1 * sn;
        __syncthreads();
        const float v0 = r2[w * 64 + lane];
        const float v1 = r2[w * 64 + 32 + lane];
        float ss = v0 * v0 + v1 * v1;
        #pragma unroll
        for (int o = 16; o; o >>= 1) ss += __shfl_xor_sync(0xffffffffu, ss, o);
        const float rms = rsqrtf(ss * (1.0f / 64.0f) + RMS_EPS);
        const size_t base = ((size_t)(b * NH + w) * SS + spos) * 64;
        g_qnh[base + lane]      = __float2half(v0 * rms);
        g_qnh[base + 32 + lane] = __float2half(v1 * rms);
        __syncthreads();
    }
}

// ------------- RoPE + per-head RMSNorm for K -> fp16 [B][HKV][S][64] -------
__global__ void rope_norm_k() {
    const int spos = blockIdx.x;
    __shared__ float r2[256];
    const int t = threadIdx.x;             // 128 threads
    const float inv = powf(10000.0f, -(float)t / 128.0f);
    float sn, cs; sincosf((float)spos * inv, &sn, &cs);
    const int w = t >> 5, lane = t & 31;
    #pragma unroll
    for (int b = 0; b < BB; b++) {
        const size_t row = (size_t)(b * SS + spos) * NQKV + 1024;
        const float x1 = g_qkv[row + t];
        const float x2 = g_qkv[row + t + 128];
        r2[t]       = x1 * cs - x2 * sn;
        r2[t + 128] = x2 * cs + x1 * sn;
        __syncthreads();
        const float v0 = r2[w * 64 + lane];
        const float v1 = r2[w * 64 + 32 + lane];
        float ss = v0 * v0 + v1 * v1;
        #pragma unroll
        for (int o = 16; o; o >>= 1) ss += __shfl_xor_sync(0xffffffffu, ss, o);
        const float rms = rsqrtf(ss * (1.0f / 64.0f) + RMS_EPS);
        const size_t base = ((size_t)(b * NKV + w) * SS + spos) * 64;
        g_knh[base + lane]      = __float2half(v0 * rms);
        g_knh[base + 32 + lane] = __float2half(v1 * rms);
        __syncthreads();
    }
}

// ------------- V transpose: g_qkv v-cols -> g_vth [B][kvh][64][S] ----------
__global__ void transpose_v() {
    const int s0  = blockIdx.x * 128;
    const int bk  = blockIdx.y;
    const int b   = bk >> 2, kvh = bk & 3;
    __shared__ float tile[128][65];
    const int t = threadIdx.x;
    #pragma unroll
    for (int i = 0; i < 8; i++) {
        int v = t + i * 256;
        int r = v >> 4, o = v & 15;
        float4 val = *(const float4*)
            &g_qkv[(size_t)(b * SS + s0 + r) * NQKV + 1280 + kvh * 64 + o * 4];
        tile[r][o * 4 + 0] = val.x;
        tile[r][o * 4 + 1] = val.y;
        tile[r][o * 4 + 2] = val.z;
        tile[r][o * 4 + 3] = val.w;
    }
    __syncthreads();
    const int w = t >> 5, lane = t & 31;
    #pragma unroll
    for (int i = 0; i < 8; i++) {
        int d = w * 8 + i;
        size_t orow = ((size_t)(b * NKV + kvh) * 64 + d) * SS + s0;
        float a0 = tile[lane * 4 + 0][d];
        float a1 = tile[lane * 4 + 1][d];
        float a2 = tile[lane * 4 + 2][d];
        float a3 = tile[lane * 4 + 3][d];
        *(__half2*)&g_vth[orow + lane * 4]     = __floats2half2_rn(a0, a1);
        *(__half2*)&g_vth[orow + lane * 4 + 2] = __floats2half2_rn(a2, a3);
    }
}

// ============================================================================
// flash attention, fp16 mma + ldmatrix + cp.async, FIXED softmax max (=8).
// ============================================================================
#define KLD 72   // smem stride in halves (144B rows, 16B-aligned)

__global__ __launch_bounds__(256, 2) void flash_attn_h16(const __nv_bfloat16* __restrict__ maskb) {
    const int q0  = blockIdx.x * 128;
    const int bh  = blockIdx.y;            // b*16 + h
    const int b   = bh >> 4, h = bh & 15;
    const int kvh = h >> 2;
    __shared__ alignas(16) __half Ks[2][64 * KLD];
    __shared__ alignas(16) __half Vs[2][64 * KLD];

    const int tid  = threadIdx.x;
    const int warp = tid >> 5, lane = tid & 31;
    const int g = lane >> 2, c = lane & 3;

    const uint32_t ksu = (uint32_t)__cvta_generic_to_shared(&Ks[0][0]);
    const uint32_t vsu = (uint32_t)__cvta_generic_to_shared(&Vs[0][0]);
    const int tile = lane >> 3, rr = lane & 7;
    const int off_ld = ((tile >> 1) * 8 + rr) * KLD + (tile & 1) * 8;

    const int qrow0 = q0 + warp * 16 + g;   // lane's rows: qrow0, qrow0+8

    unsigned QF[4][4];
    {
        const __half* q0p = g_qnh + ((size_t)(b * NH + h) * SS + qrow0) * 64;
        const __half* q1p = q0p + 8 * 64;
        #pragma unroll
        for (int kf = 0; kf < 4; kf++) {
            QF[kf][0] = *(const unsigned*)&q0p[kf * 16 + 2 * c];
            QF[kf][1] = *(const unsigned*)&q1p[kf * 16 + 2 * c];
            QF[kf][2] = *(const unsigned*)&q0p[kf * 16 + 2 * c + 8];
            QF[kf][3] = *(const unsigned*)&q1p[kf * 16 + 2 * c + 8];
        }
    }

    float O[8][4];
    #pragma unroll
    for (int nf = 0; nf < 8; nf++) { O[nf][0] = O[nf][1] = O[nf][2] = O[nf][3] = 0.f; }
    float l0 = 0.f, l1 = 0.f;

    const size_t kvbase = (size_t)(b * NKV + kvh) * SS * 64;
    const __nv_bfloat16* mrow0 = maskb + ((size_t)b * SS + qrow0) * SS;
    const __nv_bfloat16* mrow1 = mrow0 + (size_t)8 * SS;

    auto issue_tile = [&](int k0, int s) {
        const uint32_t kb = ksu + (uint32_t)s * 64 * KLD * 2;
        const uint32_t vb = vsu + (uint32_t)s * 64 * KLD * 2;
        #pragma unroll
        for (int i = 0; i < 2; i++) {
            int v = tid + i * 256;
            int r = v >> 3, o = v & 7;
            cp16(kb + (r * KLD + o * 8) * 2,
                 &g_knh[kvbase + (size_t)(k0 + r) * 64 + o * 8]);
            cp16(vb + (r * KLD + o * 8) * 2,
                 &g_vth[kvbase + (size_t)r * SS + k0 + o * 8]);
        }
        cp_commit();
    };

    issue_tile(0, 0);
    int s = 0;
    for (int k0 = 0; k0 < SS; k0 += 64) {
        cp_wait0();
        __syncthreads();
        if (k0 + 64 < SS) issue_tile(k0 + 64, s ^ 1);

        const uint32_t ksb = ksu + (uint32_t)s * 64 * KLD * 2;
        const uint32_t vsb = vsu + (uint32_t)s * 64 * KLD * 2;

        // prefetch mask for this tile (overlaps with QK^T mma below)
        float2 MK0[8], MK1[8];
        #pragma unroll
        for (int nf = 0; nf < 8; nf++) {
            MK0[nf] = __bfloat1622float2(*(const __nv_bfloat162*)&mrow0[k0 + nf * 8 + 2 * c]);
            MK1[nf] = __bfloat1622float2(*(const __nv_bfloat162*)&mrow1[k0 + nf * 8 + 2 * c]);
        }

        float S[8][4];
        #pragma unroll
        for (int nf = 0; nf < 8; nf++) S[nf][0] = S[nf][1] = S[nf][2] = S[nf][3] = 0.f;
        #pragma unroll
        for (int kf = 0; kf < 4; kf++) {
            #pragma unroll
            for (int nfp = 0; nfp < 4; nfp++) {
                unsigned b0a, b1a, b0b, b1b;
                ldsm4(b0a, b1a, b0b, b1b,
                      ksb + (uint32_t)(off_ld + nfp * 16 * KLD + kf * 16) * 2);
                mma_f16(S[2 * nfp],     QF[kf], b0a, b1a);
                mma_f16(S[2 * nfp + 1], QF[kf], b0b, b1b);
            }
        }

        unsigned PA[4][4];
        #pragma unroll
        for (int nf = 0; nf < 8; nf++) {
            float p0 = __expf(fmaf(S[nf][0], 0.125f, MK0[nf].x));
            float p1 = __expf(fmaf(S[nf][1], 0.125f, MK0[nf].y));
            float p2 = __expf(fmaf(S[nf][2], 0.125f, MK1[nf].x));
            float p3 = __expf(fmaf(S[nf][3], 0.125f, MK1[nf].y));
            l0 += p0 + p1; l1 += p2 + p3;
            const int kf = nf >> 1, hi = nf & 1;
            PA[kf][0 + 2 * hi] = h2_as_u32(__floats2half2_rn(p0, p1));
            PA[kf][1 + 2 * hi] = h2_as_u32(__floats2half2_rn(p2, p3));
        }

        #pragma unroll
        for (int kf = 0; kf < 4; kf++) {
            #pragma unroll
            for (int nfp = 0; nfp < 4; nfp++) {
                unsigned b0a, b1a, b0b, b1b;
                ldsm4(b0a, b1a, b0b, b1b,
                      vsb + (uint32_t)(off_ld + nfp * 16 * KLD + kf * 16) * 2);
                mma_f16(O[2 * nfp],     PA[kf], b0a, b1a);
                mma_f16(O[2 * nfp + 1], PA[kf], b0b, b1b);
            }
        }
        s ^= 1;
    }

    l0 += __shfl_xor_sync(0xffffffffu, l0, 1);
    l0 += __shfl_xor_sync(0xffffffffu, l0, 2);
    l1 += __shfl_xor_sync(0xffffffffu, l1, 1);
    l1 += __shfl_xor_sync(0xffffffffu, l1, 2);
    const float inv0 = 1.0f / l0, inv1 = 1.0f / l1;
    const size_t ob0 = ((size_t)b * SS + qrow0) * HID + (size_t)h * 64;
    const size_t ob1 = ob0 + (size_t)8 * HID;
    #pragma unroll
    for (int nf = 0; nf < 8; nf++) {
        *(__half2*)&g_ctxh[ob0 + nf * 8 + 2 * c] =
            __floats2half2_rn(O[nf][0] * inv0, O[nf][1] * inv0);
        *(__half2*)&g_ctxh[ob1 + nf * 8 + 2 * c] =
            __floats2half2_rn(O[nf][2] * inv1, O[nf][3] * inv1);
    }
}

// ---------------------------------------------------------------------------
extern "C" void kernel_launch(void* const* d_in, const int* in_sizes, int n_in,
                              void* d_out, int out_size) {
    const float* x    = (const float*)d_in[0];
    const float* mask = (const float*)d_in[1];
    const float* Wq   = (const float*)d_in[2];
    const float* bq   = (const float*)d_in[3];
    const float* Wk   = (const float*)d_in[4];
    const float* bk   = (const float*)d_in[5];
    const float* Wv   = (const float*)d_in[6];
    const float* bv   = (const float*)d_in[7];
    const float* Wo   = (const float*)d_in[8];
    const float* bo   = (const float*)d_in[9];
    float* out = (float*)d_out;

    __half *p_xh, *p_wqkvh, *p_woh, *p_ctxh;
    float *p_qkv, *p_b2qkv, *p_b2o;
    __nv_bfloat16* p_maskb;
    cudaGetSymbolAddress((void**)&p_xh,     g_xh);
    cudaGetSymbolAddress((void**)&p_wqkvh,  g_wqkvh);
    cudaGetSymbolAddress((void**)&p_woh,    g_woh);
    cudaGetSymbolAddress((void**)&p_ctxh,   g_ctxh);
    cudaGetSymbolAddress((void**)&p_qkv,    g_qkv);
    cudaGetSymbolAddress((void**)&p_b2qkv,  g_b2qkv);
    cudaGetSymbolAddress((void**)&p_b2o,    g_b2o);
    cudaGetSymbolAddress((void**)&p_maskb,  g_maskb);

    cudaFuncSetAttribute(gemm_h, cudaFuncAttributeMaxDynamicSharedMemorySize, GSMEM);

    // 0) single fused prep (all conversions + bias broadcast)
    prep<<<(PTOT / 4 + 255) / 256, 256>>>(x, mask, Wq, bq, Wk, bk, Wv, bv, Wo, bo);

    // 1) fused QKV projection (fp16 tensor cores, fp32 accumulate)
    gemm_h<<<dim3(NQKV / 128, MM / 128), 256, GSMEM>>>(p_xh, p_wqkvh, p_b2qkv, p_qkv,
                                                       MM, NQKV, HID);

    // 2) rope + rmsnorm + relayout (fp16 outputs), V transpose
    rope_norm_q<<<SS, 512>>>();
    rope_norm_k<<<SS, 128>>>();
    transpose_v<<<dim3(SS / 128, BB * NKV), 256>>>();

    // 3) attention (register flash, fixed-max softmax)
    flash_attn_h16<<<dim3(SS / 128, BB * NH), 256>>>(p_maskb);

    // 4) output projection straight into d_out
    gemm_h<<<dim3(HID / 128, MM / 128), 256, GSMEM>>>(p_ctxh, p_woh, p_b2o, out,
                                                      MM, HID, HID);
}

// round 16
// speedup vs baseline: 1.5008x; 1.0194x over previous
#include <cuda_runtime.h>
#include <cuda_fp16.h>
#include <cuda_bf16.h>
#include <mma.h>
#include <math.h>
#include <stdint.h>

using namespace nvcuda;

// Problem constants
#define BB   2
#define SS   2048
#define HID  1024
#define NH   16
#define NKV  4
#define MM   (BB*SS)          // 4096 rows
#define KVD  256
#define NQKV 1536             // fused projection width: 1024 q + 256 k + 256 v
#define RMS_EPS 1.1920929e-07f

// ---------------- scratch (device globals; no allocation allowed) ----------
__device__ __half g_xh[MM*HID];          // fp16 hidden
__device__ __half g_wqkvh[HID*NQKV];     // fp16 [Wq | Wk | Wv], [1024][1536]
__device__ __half g_woh[HID*HID];
__device__ float  g_b2qkv[16*NQKV];      // bias broadcast rows (16 identical)
__device__ float  g_b2o[16*HID];
__device__ float  g_qkv[(size_t)MM*NQKV];// fused projection out fp32 [M][1536]
__device__ __half g_qnh[MM*HID];         // roped+normed q fp16, [B][H][S][64]
__device__ __half g_knh[MM*KVD];         // roped+normed k fp16, [B][HKV][S][64]
__device__ __half g_vth[MM*KVD];         // V transposed fp16, [B][HKV][64][S]
__device__ __half g_ctxh[MM*HID];        // attention context fp16, [B][S][H*64]
__device__ __nv_bfloat16 g_maskb[(size_t)BB*SS*SS];  // (mask - 8) in bf16

// bit-cast helper
__device__ __forceinline__ unsigned h2_as_u32(__half2 h) {
    union { __half2 h2; unsigned u; } cv; cv.h2 = h; return cv.u;
}

// fp16 mma m16n8k16, fp32 accumulate
__device__ __forceinline__ void mma_f16(float d[4], const unsigned a[4],
                                        unsigned b0, unsigned b1) {
    asm volatile(
        "mma.sync.aligned.m16n8k16.row.col.f32.f16.f16.f32 "
        "{%0,%1,%2,%3}, {%4,%5,%6,%7}, {%8,%9}, {%0,%1,%2,%3};\n"
        : "+f"(d[0]), "+f"(d[1]), "+f"(d[2]), "+f"(d[3])
        : "r"(a[0]), "r"(a[1]), "r"(a[2]), "r"(a[3]), "r"(b0), "r"(b1));
}

// ldmatrix x4 (4 m8n8 b16 tiles)
__device__ __forceinline__ void ldsm4(unsigned& r0, unsigned& r1,
                                      unsigned& r2, unsigned& r3, uint32_t addr) {
    asm volatile("ldmatrix.sync.aligned.m8n8.x4.shared.b16 {%0,%1,%2,%3}, [%4];\n"
                 : "=r"(r0), "=r"(r1), "=r"(r2), "=r"(r3) : "r"(addr));
}

// cp.async 16B
__device__ __forceinline__ void cp16(uint32_t dst, const void* src) {
    asm volatile("cp.async.cg.shared.global [%0], [%1], 16;\n"
                 :: "r"(dst), "l"(src));
}
__device__ __forceinline__ void cp_commit() {
    asm volatile("cp.async.commit_group;\n" ::: "memory");
}
__device__ __forceinline__ void cp_wait0() {
    asm volatile("cp.async.wait_group 0;\n" ::: "memory");
}

// ============================================================================
// Single fused prep kernel (grid-strided segments)
// ============================================================================
#define PN0 (MM*HID)          // 4194304
#define PN1 (HID*NQKV)        // 1572864
#define PN2 (HID*HID)         // 1048576
#define PN3 (16*NQKV + 16*HID)// 40960
#define PN4 (BB*SS*SS)        // 8388608
#define POFF1 PN0
#define POFF2 (POFF1+PN1)
#define POFF3 (POFF2+PN2)
#define POFF4 (POFF3+PN3)
#define PTOT  (POFF4+PN4)

__global__ void prep(const float* __restrict__ x,    const float* __restrict__ mask,
                     const float* __restrict__ Wq,   const float* __restrict__ bq,
                     const float* __restrict__ Wk,   const float* __restrict__ bk,
                     const float* __restrict__ Wv,   const float* __restrict__ bv,
                     const float* __restrict__ Wo,   const float* __restrict__ bo) {
    int i = (blockIdx.x * blockDim.x + threadIdx.x) * 4;
    if (i < POFF1) {                     // x -> fp16
        float4 v = *(const float4*)&x[i];
        *(__half2*)&g_xh[i]     = __floats2half2_rn(v.x, v.y);
        *(__half2*)&g_xh[i + 2] = __floats2half2_rn(v.z, v.w);
    } else if (i < POFF2) {              // wqkv concat -> fp16
        int j = i - POFF1;
        int row = j / NQKV, col = j % NQKV;
        const float* src;
        if (col < 1024)      src = Wq + (size_t)row * 1024 + col;
        else if (col < 1280) src = Wk + (size_t)row * 256 + (col - 1024);
        else                 src = Wv + (size_t)row * 256 + (col - 1280);
        float4 v = *(const float4*)src;
        *(__half2*)&g_wqkvh[j]     = __floats2half2_rn(v.x, v.y);
        *(__half2*)&g_wqkvh[j + 2] = __floats2half2_rn(v.z, v.w);
    } else if (i < POFF3) {              // Wo -> fp16
        int j = i - POFF2;
        float4 v = *(const float4*)&Wo[j];
        *(__half2*)&g_woh[j]     = __floats2half2_rn(v.x, v.y);
        *(__half2*)&g_woh[j + 2] = __floats2half2_rn(v.z, v.w);
    } else if (i < POFF4) {              // bias broadcast
        int j = i - POFF3;
        if (j < 16 * NQKV) {
            int c = j % NQKV;
            float4 v = c < 1024 ? *(const float4*)&bq[c]
                     : (c < 1280 ? *(const float4*)&bk[c - 1024]
                                 : *(const float4*)&bv[c - 1280]);
            *(float4*)&g_b2qkv[j] = v;
        } else {
            int j2 = j - 16 * NQKV;
            *(float4*)&g_b2o[j2] = *(const float4*)&bo[j2 % HID];
        }
    } else if (i < PTOT) {               // mask -> bf16 (minus 8)
        int j = i - POFF4;
        float4 v = *(const float4*)&mask[j];
        *(__nv_bfloat162*)&g_maskb[j]     = __floats2bfloat162_rn(v.x - 8.0f, v.y - 8.0f);
        *(__nv_bfloat162*)&g_maskb[j + 2] = __floats2bfloat162_rn(v.z - 8.0f, v.w - 8.0f);
    }
}

// ============================================================================
// fp16 wmma GEMM: C[M,N] = A[M,K] @ W[K,N] + bias (acc init from bias2d rows).
// Block 128x128, 8 warps (4 row-bands x 2 col-bands), warp 32x64, k-step 32.
// 2-stage cp.async pipeline (static smem, round-12 validated config).
// ============================================================================
#define HA_LD 40       // As stride in halves (80B rows, 16B-aligned)
#define HB_LD 136      // Bs stride in halves (272B rows, 16B-aligned)
#define STG_H 9472     // halves per stage = 128*40 + 32*136

__global__ __launch_bounds__(256, 2) void gemm_h(
        const __half* __restrict__ A, const __half* __restrict__ W,
        const float* __restrict__ bias2d, float* __restrict__ C,
        int M, int N, int K) {
    __shared__ alignas(16) __half buf[2 * STG_H];   // 37.9 KB
    const uint32_t s_u32 = (uint32_t)__cvta_generic_to_shared(buf);

    const int tid  = threadIdx.x;
    const int warp = tid >> 5;
    const int wm   = warp & 3;                // row band (32 rows)
    const int wn   = warp >> 2;               // col band (64 cols)
    const int m0   = blockIdx.y * 128;
    const int n0   = blockIdx.x * 128;

    auto issue = [&](int k0, int s) {
        const uint32_t base = s_u32 + (uint32_t)s * STG_H * 2;
        #pragma unroll
        for (int i = 0; i < 2; i++) {               // A: 512 x 16B
            int v = tid + i * 256;
            int r = v >> 2, o = v & 3;
            cp16(base + (r * HA_LD + o * 8) * 2,
                 &A[(size_t)(m0 + r) * K + k0 + o * 8]);
        }
        #pragma unroll
        for (int i = 0; i < 2; i++) {               // B: 512 x 16B
            int v = tid + i * 256;
            int r = v >> 4, o = v & 15;
            cp16(base + (5120 + r * HB_LD + o * 8) * 2,
                 &W[(size_t)(k0 + r) * N + n0 + o * 8]);
        }
        cp_commit();
    };

    wmma::fragment<wmma::accumulator, 16, 16, 16, float> acc[2][4];
    #pragma unroll
    for (int i = 0; i < 2; i++)
        #pragma unroll
        for (int j = 0; j < 4; j++)
            wmma::load_matrix_sync(acc[i][j], bias2d + n0 + wn * 64 + j * 16,
                                   N, wmma::mem_row_major);

    issue(0, 0);
    int s = 0;
    for (int k0 = 0; k0 < K; k0 += 32) {
        cp_wait0();
        __syncthreads();           // data visible + prev stage fully consumed
        if (k0 + 32 < K) issue(k0 + 32, s ^ 1);

        const __half* As = buf + (size_t)s * STG_H;
        const __half* Bs = As + 5120;
        #pragma unroll
        for (int kk = 0; kk < 32; kk += 16) {
            wmma::fragment<wmma::matrix_a, 16, 16, 16, __half, wmma::row_major> a[2];
            wmma::fragment<wmma::matrix_b, 16, 16, 16, __half, wmma::row_major> b[4];
            #pragma unroll
            for (int i = 0; i < 2; i++)
                wmma::load_matrix_sync(a[i], As + (wm * 32 + i * 16) * HA_LD + kk, HA_LD);
            #pragma unroll
            for (int j = 0; j < 4; j++)
                wmma::load_matrix_sync(b[j], Bs + kk * HB_LD + wn * 64 + j * 16, HB_LD);
            #pragma unroll
            for (int i = 0; i < 2; i++)
                #pragma unroll
                for (int j = 0; j < 4; j++)
                    wmma::mma_sync(acc[i][j], a[i], b[j], acc[i][j]);
        }
        s ^= 1;
    }

    // direct fragment store to global fp32
    #pragma unroll
    for (int i = 0; i < 2; i++)
        #pragma unroll
        for (int j = 0; j < 4; j++)
            wmma::store_matrix_sync(&C[(size_t)(m0 + wm * 32 + i * 16) * N + n0 + wn * 64 + j * 16],
                                    acc[i][j], N, wmma::mem_row_major);
}

// ============================================================================
// Fused post-processing: one launch, 512 threads, segmented grid.
//   blocks [0, SS)            : q rope+rmsnorm (1 spos/block, 512 thr)
//   blocks [SS, SS+SS/4)      : k rope+rmsnorm (4 spos/block, 128-thr groups)
//   blocks [SS+SS/4, +128)    : v transpose (1 tile/block, 512 thr)
// ============================================================================
#define PB_K  (SS/4)           // 512 k-blocks
#define PB_V  128              // v-transpose blocks
#define PB_TOT (SS + PB_K + PB_V)

__global__ __launch_bounds__(512) void postproc() {
    const int bi = blockIdx.x;
    const int t  = threadIdx.x;

    if (bi < SS) {
        // ---------------- q rope + rmsnorm (spos = bi) ----------------
        __shared__ float r2[1024];
        const int spos = bi;
        const float inv = powf(10000.0f, -(float)t / 512.0f);
        float sn, cs; sincosf((float)spos * inv, &sn, &cs);
        const int w = t >> 5, lane = t & 31;
        #pragma unroll
        for (int b = 0; b < BB; b++) {
            const size_t row = (size_t)(b * SS + spos) * NQKV;
            const float x1 = g_qkv[row + t];
            const float x2 = g_qkv[row + t + 512];
            r2[t]       = x1 * cs - x2 * sn;
            r2[t + 512] = x2 * cs + x1 * sn;
            __syncthreads();
            const float v0 = r2[w * 64 + lane];
            const float v1 = r2[w * 64 + 32 + lane];
            float ss = v0 * v0 + v1 * v1;
            #pragma unroll
            for (int o = 16; o; o >>= 1) ss += __shfl_xor_sync(0xffffffffu, ss, o);
            const float rms = rsqrtf(ss * (1.0f / 64.0f) + RMS_EPS);
            const size_t base = ((size_t)(b * NH + w) * SS + spos) * 64;
            g_qnh[base + lane]      = __float2half(v0 * rms);
            g_qnh[base + 32 + lane] = __float2half(v1 * rms);
            __syncthreads();
        }
    } else if (bi < SS + PB_K) {
        // ------------- k rope + rmsnorm (4 spos/block, 128-thr groups) -----
        __shared__ float r2k[4][256];
        const int grp = t >> 7;             // 0..3
        const int gt  = t & 127;            // thread within group
        const int spos = (bi - SS) * 4 + grp;
        const unsigned barid = 1 + grp;     // named barrier per group
        const float inv = powf(10000.0f, -(float)gt / 128.0f);
        float sn, cs; sincosf((float)spos * inv, &sn, &cs);
        const int w = gt >> 5, lane = gt & 31;
        #pragma unroll
        for (int b = 0; b < BB; b++) {
            const size_t row = (size_t)(b * SS + spos) * NQKV + 1024;
            const float x1 = g_qkv[row + gt];
            const float x2 = g_qkv[row + gt + 128];
            r2k[grp][gt]       = x1 * cs - x2 * sn;
            r2k[grp][gt + 128] = x2 * cs + x1 * sn;
            asm volatile("bar.sync %0, 128;" :: "r"(barid) : "memory");
            const float v0 = r2k[grp][w * 64 + lane];
            const float v1 = r2k[grp][w * 64 + 32 + lane];
            float ss = v0 * v0 + v1 * v1;
            #pragma unroll
            for (int o = 16; o; o >>= 1) ss += __shfl_xor_sync(0xffffffffu, ss, o);
            const float rms = rsqrtf(ss * (1.0f / 64.0f) + RMS_EPS);
            const size_t base = ((size_t)(b * NKV + w) * SS + spos) * 64;
            g_knh[base + lane]      = __float2half(v0 * rms);
            g_knh[base + 32 + lane] = __float2half(v1 * rms);
            asm volatile("bar.sync %0, 128;" :: "r"(barid) : "memory");
        }
    } else {
        // ---------------- v transpose (1 tile/block, 512 thr) --------------
        __shared__ float tile[128][65];
        const int vb  = bi - SS - PB_K;      // 0..127
        const int s0  = (vb & 15) * 128;     // 16 s-tiles
        const int bk  = vb >> 4;             // 0..7 = b*4 + kvh
        const int b   = bk >> 2, kvh = bk & 3;
        #pragma unroll
        for (int i = 0; i < 4; i++) {        // 2048 float4, 512 thr
            int v = t + i * 512;
            int r = v >> 4, o = v & 15;
            float4 val = *(const float4*)
                &g_qkv[(size_t)(b * SS + s0 + r) * NQKV + 1280 + kvh * 64 + o * 4];
            tile[r][o * 4 + 0] = val.x;
            tile[r][o * 4 + 1] = val.y;
            tile[r][o * 4 + 2] = val.z;
            tile[r][o * 4 + 3] = val.w;
        }
        __syncthreads();
        const int w = t >> 5, lane = t & 31;  // 16 warps x 4 dims
        #pragma unroll
        for (int i = 0; i < 4; i++) {
            int d = w * 4 + i;
            size_t orow = ((size_t)(b * NKV + kvh) * 64 + d) * SS + s0;
            float a0 = tile[lane * 4 + 0][d];
            float a1 = tile[lane * 4 + 1][d];
            float a2 = tile[lane * 4 + 2][d];
            float a3 = tile[lane * 4 + 3][d];
            *(__half2*)&g_vth[orow + lane * 4]     = __floats2half2_rn(a0, a1);
            *(__half2*)&g_vth[orow + lane * 4 + 2] = __floats2half2_rn(a2, a3);
        }
    }
}

// ============================================================================
// flash attention, fp16 mma + ldmatrix + cp.async, FIXED softmax max (=8).
// ============================================================================
#define KLD 72   // smem stride in halves (144B rows, 16B-aligned)

__global__ __launch_bounds__(256, 2) void flash_attn_h16(const __nv_bfloat16* __restrict__ maskb) {
    const int q0  = blockIdx.x * 128;
    const int bh  = blockIdx.y;            // b*16 + h
    const int b   = bh >> 4, h = bh & 15;
    const int kvh = h >> 2;
    __shared__ alignas(16) __half Ks[2][64 * KLD];
    __shared__ alignas(16) __half Vs[2][64 * KLD];

    const int tid  = threadIdx.x;
    const int warp = tid >> 5, lane = tid & 31;
    const int g = lane >> 2, c = lane & 3;

    const uint32_t ksu = (uint32_t)__cvta_generic_to_shared(&Ks[0][0]);
    const uint32_t vsu = (uint32_t)__cvta_generic_to_shared(&Vs[0][0]);
    const int tile = lane >> 3, rr = lane & 7;
    const int off_ld = ((tile >> 1) * 8 + rr) * KLD + (tile & 1) * 8;

    const int qrow0 = q0 + warp * 16 + g;   // lane's rows: qrow0, qrow0+8

    unsigned QF[4][4];
    {
        const __half* q0p = g_qnh + ((size_t)(b * NH + h) * SS + qrow0) * 64;
        const __half* q1p = q0p + 8 * 64;
        #pragma unroll
        for (int kf = 0; kf < 4; kf++) {
            QF[kf][0] = *(const unsigned*)&q0p[kf * 16 + 2 * c];
            QF[kf][1] = *(const unsigned*)&q1p[kf * 16 + 2 * c];
            QF[kf][2] = *(const unsigned*)&q0p[kf * 16 + 2 * c + 8];
            QF[kf][3] = *(const unsigned*)&q1p[kf * 16 + 2 * c + 8];
        }
    }

    float O[8][4];
    #pragma unroll
    for (int nf = 0; nf < 8; nf++) { O[nf][0] = O[nf][1] = O[nf][2] = O[nf][3] = 0.f; }
    float l0 = 0.f, l1 = 0.f;

    const size_t kvbase = (size_t)(b * NKV + kvh) * SS * 64;
    const __nv_bfloat16* mrow0 = maskb + ((size_t)b * SS + qrow0) * SS;
    const __nv_bfloat16* mrow1 = mrow0 + (size_t)8 * SS;

    auto issue_tile = [&](int k0, int s) {
        const uint32_t kb = ksu + (uint32_t)s * 64 * KLD * 2;
        const uint32_t vb = vsu + (uint32_t)s * 64 * KLD * 2;
        #pragma unroll
        for (int i = 0; i < 2; i++) {
            int v = tid + i * 256;
            int r = v >> 3, o = v & 7;
            cp16(kb + (r * KLD + o * 8) * 2,
                 &g_knh[kvbase + (size_t)(k0 + r) * 64 + o * 8]);
            cp16(vb + (r * KLD + o * 8) * 2,
                 &g_vth[kvbase + (size_t)r * SS + k0 + o * 8]);
        }
        cp_commit();
    };

    issue_tile(0, 0);
    int s = 0;
    for (int k0 = 0; k0 < SS; k0 += 64) {
        cp_wait0();
        __syncthreads();
        if (k0 + 64 < SS) issue_tile(k0 + 64, s ^ 1);

        const uint32_t ksb = ksu + (uint32_t)s * 64 * KLD * 2;
        const uint32_t vsb = vsu + (uint32_t)s * 64 * KLD * 2;

        // prefetch mask for this tile (overlaps with QK^T mma below)
        float2 MK0[8], MK1[8];
        #pragma unroll
        for (int nf = 0; nf < 8; nf++) {
            MK0[nf] = __bfloat1622float2(*(const __nv_bfloat162*)&mrow0[k0 + nf * 8 + 2 * c]);
            MK1[nf] = __bfloat1622float2(*(const __nv_bfloat162*)&mrow1[k0 + nf * 8 + 2 * c]);
        }

        float S[8][4];
        #pragma unroll
        for (int nf = 0; nf < 8; nf++) S[nf][0] = S[nf][1] = S[nf][2] = S[nf][3] = 0.f;
        #pragma unroll
        for (int kf = 0; kf < 4; kf++) {
            #pragma unroll
            for (int nfp = 0; nfp < 4; nfp++) {
                unsigned b0a, b1a, b0b, b1b;
                ldsm4(b0a, b1a, b0b, b1b,
                      ksb + (uint32_t)(off_ld + nfp * 16 * KLD + kf * 16) * 2);
                mma_f16(S[2 * nfp],     QF[kf], b0a, b1a);
                mma_f16(S[2 * nfp + 1], QF[kf], b0b, b1b);
            }
        }

        unsigned PA[4][4];
        #pragma unroll
        for (int nf = 0; nf < 8; nf++) {
            float p0 = __expf(fmaf(S[nf][0], 0.125f, MK0[nf].x));
            float p1 = __expf(fmaf(S[nf][1], 0.125f, MK0[nf].y));
            float p2 = __expf(fmaf(S[nf][2], 0.125f, MK1[nf].x));
            float p3 = __expf(fmaf(S[nf][3], 0.125f, MK1[nf].y));
            l0 += p0 + p1; l1 += p2 + p3;
            const int kf = nf >> 1, hi = nf & 1;
            PA[kf][0 + 2 * hi] = h2_as_u32(__floats2half2_rn(p0, p1));
            PA[kf][1 + 2 * hi] = h2_as_u32(__floats2half2_rn(p2, p3));
        }

        #pragma unroll
        for (int kf = 0; kf < 4; kf++) {
            #pragma unroll
            for (int nfp = 0; nfp < 4; nfp++) {
                unsigned b0a, b1a, b0b, b1b;
                ldsm4(b0a, b1a, b0b, b1b,
                      vsb + (uint32_t)(off_ld + nfp * 16 * KLD + kf * 16) * 2);
                mma_f16(O[2 * nfp],     PA[kf], b0a, b1a);
                mma_f16(O[2 * nfp + 1], PA[kf], b0b, b1b);
            }
        }
        s ^= 1;
    }

    l0 += __shfl_xor_sync(0xffffffffu, l0, 1);
    l0 += __shfl_xor_sync(0xffffffffu, l0, 2);
    l1 += __shfl_xor_sync(0xffffffffu, l1, 1);
    l1 += __shfl_xor_sync(0xffffffffu, l1, 2);
    const float inv0 = 1.0f / l0, inv1 = 1.0f / l1;
    const size_t ob0 = ((size_t)b * SS + qrow0) * HID + (size_t)h * 64;
    const size_t ob1 = ob0 + (size_t)8 * HID;
    #pragma unroll
    for (int nf = 0; nf < 8; nf++) {
        *(__half2*)&g_ctxh[ob0 + nf * 8 + 2 * c] =
            __floats2half2_rn(O[nf][0] * inv0, O[nf][1] * inv0);
        *(__half2*)&g_ctxh[ob1 + nf * 8 + 2 * c] =
            __floats2half2_rn(O[nf][2] * inv1, O[nf][3] * inv1);
    }
}

// ---------------------------------------------------------------------------
extern "C" void kernel_launch(void* const* d_in, const int* in_sizes, int n_in,
                              void* d_out, int out_size) {
    const float* x    = (const float*)d_in[0];
    const float* mask = (const float*)d_in[1];
    const float* Wq   = (const float*)d_in[2];
    const float* bq   = (const float*)d_in[3];
    const float* Wk   = (const float*)d_in[4];
    const float* bk   = (const float*)d_in[5];
    const float* Wv   = (const float*)d_in[6];
    const float* bv   = (const float*)d_in[7];
    const float* Wo   = (const float*)d_in[8];
    const float* bo   = (const float*)d_in[9];
    float* out = (float*)d_out;

    __half *p_xh, *p_wqkvh, *p_woh, *p_ctxh;
    float *p_qkv, *p_b2qkv, *p_b2o;
    __nv_bfloat16* p_maskb;
    cudaGetSymbolAddress((void**)&p_xh,     g_xh);
    cudaGetSymbolAddress((void**)&p_wqkvh,  g_wqkvh);
    cudaGetSymbolAddress((void**)&p_woh,    g_woh);
    cudaGetSymbolAddress((void**)&p_ctxh,   g_ctxh);
    cudaGetSymbolAddress((void**)&p_qkv,    g_qkv);
    cudaGetSymbolAddress((void**)&p_b2qkv,  g_b2qkv);
    cudaGetSymbolAddress((void**)&p_b2o,    g_b2o);
    cudaGetSymbolAddress((void**)&p_maskb,  g_maskb);

    // 0) single fused prep (all conversions + bias broadcast)
    prep<<<(PTOT / 4 + 255) / 256, 256>>>(x, mask, Wq, bq, Wk, bk, Wv, bv, Wo, bo);

    // 1) fused QKV projection (fp16 tensor cores, fp32 accumulate)
    gemm_h<<<dim3(NQKV / 128, MM / 128), 256>>>(p_xh, p_wqkvh, p_b2qkv, p_qkv,
                                                MM, NQKV, HID);

    // 2) fused rope(q) + rope(k) + v-transpose — single launch
    postproc<<<PB_TOT, 512>>>();

    // 3) attention (register flash, fixed-max softmax)
    flash_attn_h16<<<dim3(SS / 128, BB * NH), 256>>>(p_maskb);

    // 4) output projection straight into d_out
    gemm_h<<<dim3(HID / 128, MM / 128), 256>>>(p_ctxh, p_woh, p_b2o, out,
                                               MM, HID, HID);
}

// round 17
// speedup vs baseline: 1.5484x; 1.0317x over previous
#include <cuda_runtime.h>
#include <cuda_fp16.h>
#include <cuda_bf16.h>
#include <mma.h>
#include <math.h>
#include <stdint.h>

using namespace nvcuda;

// Problem constants
#define BB   2
#define SS   2048
#define HID  1024
#define NH   16
#define NKV  4
#define MM   (BB*SS)          // 4096 rows
#define KVD  256
#define NQKV 1536             // fused projection width: 1024 q + 256 k + 256 v
#define RMS_EPS 1.1920929e-07f

// ---------------- scratch (device globals; no allocation allowed) ----------
__device__ __half g_xh[MM*HID];          // fp16 hidden
__device__ __half g_wqkvh[HID*NQKV];     // fp16 [Wq | Wk | Wv], [1024][1536]
__device__ __half g_woh[HID*HID];
__device__ float  g_b2qkv[16*NQKV];      // bias broadcast rows (16 identical)
__device__ float  g_b2o[16*HID];
__device__ float  g_qkv[(size_t)MM*NQKV];// fused projection out fp32 [M][1536]
__device__ __half g_qnh[MM*HID];         // roped+normed q fp16, [B][H][S][64]
__device__ __half g_knh[MM*KVD];         // roped+normed k fp16, [B][HKV][S][64]
__device__ __half g_vth[MM*KVD];         // V transposed fp16, [B][HKV][64][S]
__device__ __half g_ctxh[MM*HID];        // attention context fp16, [B][S][H*64]
__device__ __nv_bfloat16 g_maskb[(size_t)BB*SS*SS];  // (mask - 8) in bf16

// bit-cast helper
__device__ __forceinline__ unsigned h2_as_u32(__half2 h) {
    union { __half2 h2; unsigned u; } cv; cv.h2 = h; return cv.u;
}

// fp16 mma m16n8k16, fp32 accumulate
__device__ __forceinline__ void mma_f16(float d[4], const unsigned a[4],
                                        unsigned b0, unsigned b1) {
    asm volatile(
        "mma.sync.aligned.m16n8k16.row.col.f32.f16.f16.f32 "
        "{%0,%1,%2,%3}, {%4,%5,%6,%7}, {%8,%9}, {%0,%1,%2,%3};\n"
        : "+f"(d[0]), "+f"(d[1]), "+f"(d[2]), "+f"(d[3])
        : "r"(a[0]), "r"(a[1]), "r"(a[2]), "r"(a[3]), "r"(b0), "r"(b1));
}

// ldmatrix x4 (4 m8n8 b16 tiles)
__device__ __forceinline__ void ldsm4(unsigned& r0, unsigned& r1,
                                      unsigned& r2, unsigned& r3, uint32_t addr) {
    asm volatile("ldmatrix.sync.aligned.m8n8.x4.shared.b16 {%0,%1,%2,%3}, [%4];\n"
                 : "=r"(r0), "=r"(r1), "=r"(r2), "=r"(r3) : "r"(addr));
}

// cp.async 16B
__device__ __forceinline__ void cp16(uint32_t dst, const void* src) {
    asm volatile("cp.async.cg.shared.global [%0], [%1], 16;\n"
                 :: "r"(dst), "l"(src));
}
__device__ __forceinline__ void cp_commit() {
    asm volatile("cp.async.commit_group;\n" ::: "memory");
}
__device__ __forceinline__ void cp_wait0() {
    asm volatile("cp.async.wait_group 0;\n" ::: "memory");
}

// ============================================================================
// Single fused prep kernel (grid-strided segments)
// ============================================================================
#define PN0 (MM*HID)          // 4194304
#define PN1 (HID*NQKV)        // 1572864
#define PN2 (HID*HID)         // 1048576
#define PN3 (16*NQKV + 16*HID)// 40960
#define PN4 (BB*SS*SS)        // 8388608
#define POFF1 PN0
#define POFF2 (POFF1+PN1)
#define POFF3 (POFF2+PN2)
#define POFF4 (POFF3+PN3)
#define PTOT  (POFF4+PN4)

__global__ void prep(const float* __restrict__ x,    const float* __restrict__ mask,
                     const float* __restrict__ Wq,   const float* __restrict__ bq,
                     const float* __restrict__ Wk,   const float* __restrict__ bk,
                     const float* __restrict__ Wv,   const float* __restrict__ bv,
                     const float* __restrict__ Wo,   const float* __restrict__ bo) {
    int i = (blockIdx.x * blockDim.x + threadIdx.x) * 4;
    if (i < POFF1) {                     // x -> fp16
        float4 v = *(const float4*)&x[i];
        *(__half2*)&g_xh[i]     = __floats2half2_rn(v.x, v.y);
        *(__half2*)&g_xh[i + 2] = __floats2half2_rn(v.z, v.w);
    } else if (i < POFF2) {              // wqkv concat -> fp16
        int j = i - POFF1;
        int row = j / NQKV, col = j % NQKV;
        const float* src;
        if (col < 1024)      src = Wq + (size_t)row * 1024 + col;
        else if (col < 1280) src = Wk + (size_t)row * 256 + (col - 1024);
        else                 src = Wv + (size_t)row * 256 + (col - 1280);
        float4 v = *(const float4*)src;
        *(__half2*)&g_wqkvh[j]     = __floats2half2_rn(v.x, v.y);
        *(__half2*)&g_wqkvh[j + 2] = __floats2half2_rn(v.z, v.w);
    } else if (i < POFF3) {              // Wo -> fp16
        int j = i - POFF2;
        float4 v = *(const float4*)&Wo[j];
        *(__half2*)&g_woh[j]     = __floats2half2_rn(v.x, v.y);
        *(__half2*)&g_woh[j + 2] = __floats2half2_rn(v.z, v.w);
    } else if (i < POFF4) {              // bias broadcast
        int j = i - POFF3;
        if (j < 16 * NQKV) {
            int c = j % NQKV;
            float4 v = c < 1024 ? *(const float4*)&bq[c]
                     : (c < 1280 ? *(const float4*)&bk[c - 1024]
                                 : *(const float4*)&bv[c - 1280]);
            *(float4*)&g_b2qkv[j] = v;
        } else {
            int j2 = j - 16 * NQKV;
            *(float4*)&g_b2o[j2] = *(const float4*)&bo[j2 % HID];
        }
    } else if (i < PTOT) {               // mask -> bf16 (minus 8)
        int j = i - POFF4;
        float4 v = *(const float4*)&mask[j];
        *(__nv_bfloat162*)&g_maskb[j]     = __floats2bfloat162_rn(v.x - 8.0f, v.y - 8.0f);
        *(__nv_bfloat162*)&g_maskb[j + 2] = __floats2bfloat162_rn(v.z - 8.0f, v.w - 8.0f);
    }
}

// ============================================================================
// fp16 wmma GEMM (round-12 validated): block 128x128, 8 warps, k-step 32,
// 2-stage cp.async, static smem, direct fragment stores.
// ============================================================================
#define HA_LD 40
#define HB_LD 136
#define STG_H 9472

__global__ __launch_bounds__(256, 2) void gemm_h(
        const __half* __restrict__ A, const __half* __restrict__ W,
        const float* __restrict__ bias2d, float* __restrict__ C,
        int M, int N, int K) {
    __shared__ alignas(16) __half buf[2 * STG_H];
    const uint32_t s_u32 = (uint32_t)__cvta_generic_to_shared(buf);

    const int tid  = threadIdx.x;
    const int warp = tid >> 5;
    const int wm   = warp & 3;
    const int wn   = warp >> 2;
    const int m0   = blockIdx.y * 128;
    const int n0   = blockIdx.x * 128;

    auto issue = [&](int k0, int s) {
        const uint32_t base = s_u32 + (uint32_t)s * STG_H * 2;
        #pragma unroll
        for (int i = 0; i < 2; i++) {
            int v = tid + i * 256;
            int r = v >> 2, o = v & 3;
            cp16(base + (r * HA_LD + o * 8) * 2,
                 &A[(size_t)(m0 + r) * K + k0 + o * 8]);
        }
        #pragma unroll
        for (int i = 0; i < 2; i++) {
            int v = tid + i * 256;
            int r = v >> 4, o = v & 15;
            cp16(base + (5120 + r * HB_LD + o * 8) * 2,
                 &W[(size_t)(k0 + r) * N + n0 + o * 8]);
        }
        cp_commit();
    };

    wmma::fragment<wmma::accumulator, 16, 16, 16, float> acc[2][4];
    #pragma unroll
    for (int i = 0; i < 2; i++)
        #pragma unroll
        for (int j = 0; j < 4; j++)
            wmma::load_matrix_sync(acc[i][j], bias2d + n0 + wn * 64 + j * 16,
                                   N, wmma::mem_row_major);

    issue(0, 0);
    int s = 0;
    for (int k0 = 0; k0 < K; k0 += 32) {
        cp_wait0();
        __syncthreads();
        if (k0 + 32 < K) issue(k0 + 32, s ^ 1);

        const __half* As = buf + (size_t)s * STG_H;
        const __half* Bs = As + 5120;
        #pragma unroll
        for (int kk = 0; kk < 32; kk += 16) {
            wmma::fragment<wmma::matrix_a, 16, 16, 16, __half, wmma::row_major> a[2];
            wmma::fragment<wmma::matrix_b, 16, 16, 16, __half, wmma::row_major> b[4];
            #pragma unroll
            for (int i = 0; i < 2; i++)
                wmma::load_matrix_sync(a[i], As + (wm * 32 + i * 16) * HA_LD + kk, HA_LD);
            #pragma unroll
            for (int j = 0; j < 4; j++)
                wmma::load_matrix_sync(b[j], Bs + kk * HB_LD + wn * 64 + j * 16, HB_LD);
            #pragma unroll
            for (int i = 0; i < 2; i++)
                #pragma unroll
                for (int j = 0; j < 4; j++)
                    wmma::mma_sync(acc[i][j], a[i], b[j], acc[i][j]);
        }
        s ^= 1;
    }

    #pragma unroll
    for (int i = 0; i < 2; i++)
        #pragma unroll
        for (int j = 0; j < 4; j++)
            wmma::store_matrix_sync(&C[(size_t)(m0 + wm * 32 + i * 16) * N + n0 + wn * 64 + j * 16],
                                    acc[i][j], N, wmma::mem_row_major);
}

// ------------- RoPE + per-head RMSNorm for Q -> fp16 [B][H][S][64] ---------
__global__ void rope_norm_q() {
    const int spos = blockIdx.x;
    __shared__ float r2[1024];
    const int t = threadIdx.x;             // 512 threads
    const float inv = powf(10000.0f, -(float)t / 512.0f);
    float sn, cs; sincosf((float)spos * inv, &sn, &cs);
    const int w = t >> 5, lane = t & 31;
    #pragma unroll
    for (int b = 0; b < BB; b++) {
        const size_t row = (size_t)(b * SS + spos) * NQKV;
        const float x1 = g_qkv[row + t];
        const float x2 = g_qkv[row + t + 512];
        r2[t]       = x1 * cs - x2 * sn;
        r2[t + 512] = x2 * cs + x1 * sn;
        __syncthreads();
        const float v0 = r2[w * 64 + lane];
        const float v1 = r2[w * 64 + 32 + lane];
        float ss = v0 * v0 + v1 * v1;
        #pragma unroll
        for (int o = 16; o; o >>= 1) ss += __shfl_xor_sync(0xffffffffu, ss, o);
        const float rms = rsqrtf(ss * (1.0f / 64.0f) + RMS_EPS);
        const size_t base = ((size_t)(b * NH + w) * SS + spos) * 64;
        g_qnh[base + lane]      = __float2half(v0 * rms);
        g_qnh[base + 32 + lane] = __float2half(v1 * rms);
        __syncthreads();
    }
}

// ------------- RoPE + per-head RMSNorm for K -> fp16 [B][HKV][S][64] -------
__global__ void rope_norm_k() {
    const int spos = blockIdx.x;
    __shared__ float r2[256];
    const int t = threadIdx.x;             // 128 threads
    const float inv = powf(10000.0f, -(float)t / 128.0f);
    float sn, cs; sincosf((float)spos * inv, &sn, &cs);
    const int w = t >> 5, lane = t & 31;
    #pragma unroll
    for (int b = 0; b < BB; b++) {
        const size_t row = (size_t)(b * SS + spos) * NQKV + 1024;
        const float x1 = g_qkv[row + t];
        const float x2 = g_qkv[row + t + 128];
        r2[t]       = x1 * cs - x2 * sn;
        r2[t + 128] = x2 * cs + x1 * sn;
        __syncthreads();
        const float v0 = r2[w * 64 + lane];
        const float v1 = r2[w * 64 + 32 + lane];
        float ss = v0 * v0 + v1 * v1;
        #pragma unroll
        for (int o = 16; o; o >>= 1) ss += __shfl_xor_sync(0xffffffffu, ss, o);
        const float rms = rsqrtf(ss * (1.0f / 64.0f) + RMS_EPS);
        const size_t base = ((size_t)(b * NKV + w) * SS + spos) * 64;
        g_knh[base + lane]      = __float2half(v0 * rms);
        g_knh[base + 32 + lane] = __float2half(v1 * rms);
        __syncthreads();
    }
}

// ------------- V transpose: g_qkv v-cols -> g_vth [B][kvh][64][S] ----------
__global__ void transpose_v() {
    const int s0  = blockIdx.x * 128;
    const int bk  = blockIdx.y;
    const int b   = bk >> 2, kvh = bk & 3;
    __shared__ float tile[128][65];
    const int t = threadIdx.x;
    #pragma unroll
    for (int i = 0; i < 8; i++) {
        int v = t + i * 256;
        int r = v >> 4, o = v & 15;
        float4 val = *(const float4*)
            &g_qkv[(size_t)(b * SS + s0 + r) * NQKV + 1280 + kvh * 64 + o * 4];
        tile[r][o * 4 + 0] = val.x;
        tile[r][o * 4 + 1] = val.y;
        tile[r][o * 4 + 2] = val.z;
        tile[r][o * 4 + 3] = val.w;
    }
    __syncthreads();
    const int w = t >> 5, lane = t & 31;
    #pragma unroll
    for (int i = 0; i < 8; i++) {
        int d = w * 8 + i;
        size_t orow = ((size_t)(b * NKV + kvh) * 64 + d) * SS + s0;
        float a0 = tile[lane * 4 + 0][d];
        float a1 = tile[lane * 4 + 1][d];
        float a2 = tile[lane * 4 + 2][d];
        float a3 = tile[lane * 4 + 3][d];
        *(__half2*)&g_vth[orow + lane * 4]     = __floats2half2_rn(a0, a1);
        *(__half2*)&g_vth[orow + lane * 4 + 2] = __floats2half2_rn(a2, a3);
    }
}

// ============================================================================
// flash attention: 4 warps/block, 32 q-rows/warp (2 row-sets) -> each ldmatrix
// B-fragment feeds 4 mma instead of 2, halving smem read traffic per FLOP.
// fp16 mma + cp.async double-buffer, FIXED softmax max (=8).
// ============================================================================
#define KLD 72   // smem stride in halves (144B rows, 16B-aligned)

__global__ __launch_bounds__(128, 2) void flash_attn_h16(const __nv_bfloat16* __restrict__ maskb) {
    const int q0  = blockIdx.x * 128;
    const int bh  = blockIdx.y;            // b*16 + h
    const int b   = bh >> 4, h = bh & 15;
    const int kvh = h >> 2;
    __shared__ alignas(16) __half Ks[2][64 * KLD];
    __shared__ alignas(16) __half Vs[2][64 * KLD];

    const int tid  = threadIdx.x;          // 128 threads, 4 warps
    const int warp = tid >> 5, lane = tid & 31;
    const int g = lane >> 2, c = lane & 3;

    const uint32_t ksu = (uint32_t)__cvta_generic_to_shared(&Ks[0][0]);
    const uint32_t vsu = (uint32_t)__cvta_generic_to_shared(&Vs[0][0]);
    const int tile = lane >> 3, rr = lane & 7;
    const int off_ld = ((tile >> 1) * 8 + rr) * KLD + (tile & 1) * 8;

    const int r0 = q0 + warp * 32 + g;     // warp rows: r0, r0+8, r0+16, r0+24

    // Q fragments: 2 row-sets x 4 k-chunks
    unsigned QF[2][4][4];
    {
        const __half* qp = g_qnh + ((size_t)(b * NH + h) * SS + r0) * 64;
        #pragma unroll
        for (int st = 0; st < 2; st++) {
            const __half* a0 = qp + (size_t)(st * 16) * 64;
            const __half* a1 = a0 + 8 * 64;
            #pragma unroll
            for (int kf = 0; kf < 4; kf++) {
                QF[st][kf][0] = *(const unsigned*)&a0[kf * 16 + 2 * c];
                QF[st][kf][1] = *(const unsigned*)&a1[kf * 16 + 2 * c];
                QF[st][kf][2] = *(const unsigned*)&a0[kf * 16 + 2 * c + 8];
                QF[st][kf][3] = *(const unsigned*)&a1[kf * 16 + 2 * c + 8];
            }
        }
    }

    float O[2][8][4];
    #pragma unroll
    for (int st = 0; st < 2; st++)
        #pragma unroll
        for (int nf = 0; nf < 8; nf++)
            O[st][nf][0] = O[st][nf][1] = O[st][nf][2] = O[st][nf][3] = 0.f;
    float lsum[2][2] = {{0.f, 0.f}, {0.f, 0.f}};

    const size_t kvbase = (size_t)(b * NKV + kvh) * SS * 64;
    const __nv_bfloat16* mrow[2][2];
    #pragma unroll
    for (int st = 0; st < 2; st++) {
        mrow[st][0] = maskb + ((size_t)b * SS + r0 + st * 16) * SS;
        mrow[st][1] = mrow[st][0] + (size_t)8 * SS;
    }

    auto issue_tile = [&](int k0, int s) {
        const uint32_t kb = ksu + (uint32_t)s * 64 * KLD * 2;
        const uint32_t vb = vsu + (uint32_t)s * 64 * KLD * 2;
        #pragma unroll
        for (int i = 0; i < 4; i++) {          // 512 granules each, 128 thr
            int v = tid + i * 128;
            int r = v >> 3, o = v & 7;
            cp16(kb + (r * KLD + o * 8) * 2,
                 &g_knh[kvbase + (size_t)(k0 + r) * 64 + o * 8]);
            cp16(vb + (r * KLD + o * 8) * 2,
                 &g_vth[kvbase + (size_t)r * SS + k0 + o * 8]);
        }
        cp_commit();
    };

    issue_tile(0, 0);
    int s = 0;
    for (int k0 = 0; k0 < SS; k0 += 64) {
        cp_wait0();
        __syncthreads();
        if (k0 + 64 < SS) issue_tile(k0 + 64, s ^ 1);

        const uint32_t ksb = ksu + (uint32_t)s * 64 * KLD * 2;
        const uint32_t vsb = vsu + (uint32_t)s * 64 * KLD * 2;

        // ---- S = Q @ K^T : each ldsm4 feeds both row-sets (4 mma) ----
        float S[2][8][4];
        #pragma unroll
        for (int st = 0; st < 2; st++)
            #pragma unroll
            for (int nf = 0; nf < 8; nf++)
                S[st][nf][0] = S[st][nf][1] = S[st][nf][2] = S[st][nf][3] = 0.f;
        #pragma unroll
        for (int kf = 0; kf < 4; kf++) {
            #pragma unroll
            for (int nfp = 0; nfp < 4; nfp++) {
                unsigned b0a, b1a, b0b, b1b;
                ldsm4(b0a, b1a, b0b, b1b,
                      ksb + (uint32_t)(off_ld + nfp * 16 * KLD + kf * 16) * 2);
                mma_f16(S[0][2 * nfp],     QF[0][kf], b0a, b1a);
                mma_f16(S[0][2 * nfp + 1], QF[0][kf], b0b, b1b);
                mma_f16(S[1][2 * nfp],     QF[1][kf], b0a, b1a);
                mma_f16(S[1][2 * nfp + 1], QF[1][kf], b0b, b1b);
            }
        }

        // ---- fixed-max softmax: p = exp(s/8 + (mask-8)) ----
        unsigned PA[2][4][4];
        #pragma unroll
        for (int st = 0; st < 2; st++) {
            #pragma unroll
            for (int nf = 0; nf < 8; nf++) {
                float2 mk0 = __bfloat1622float2(
                    *(const __nv_bfloat162*)&mrow[st][0][k0 + nf * 8 + 2 * c]);
                float2 mk1 = __bfloat1622float2(
                    *(const __nv_bfloat162*)&mrow[st][1][k0 + nf * 8 + 2 * c]);
                float p0 = __expf(fmaf(S[st][nf][0], 0.125f, mk0.x));
                float p1 = __expf(fmaf(S[st][nf][1], 0.125f, mk0.y));
                float p2 = __expf(fmaf(S[st][nf][2], 0.125f, mk1.x));
                float p3 = __expf(fmaf(S[st][nf][3], 0.125f, mk1.y));
                lsum[st][0] += p0 + p1; lsum[st][1] += p2 + p3;
                const int kf = nf >> 1, hi = nf & 1;
                PA[st][kf][0 + 2 * hi] = h2_as_u32(__floats2half2_rn(p0, p1));
                PA[st][kf][1 + 2 * hi] = h2_as_u32(__floats2half2_rn(p2, p3));
            }
        }

        // ---- O += P @ V : each ldsm4 feeds both row-sets ----
        #pragma unroll
        for (int kf = 0; kf < 4; kf++) {
            #pragma unroll
            for (int nfp = 0; nfp < 4; nfp++) {
                unsigned b0a, b1a, b0b, b1b;
                ldsm4(b0a, b1a, b0b, b1b,
                      vsb + (uint32_t)(off_ld + nfp * 16 * KLD + kf * 16) * 2);
                mma_f16(O[0][2 * nfp],     PA[0][kf], b0a, b1a);
                mma_f16(O[0][2 * nfp + 1], PA[0][kf], b0b, b1b);
                mma_f16(O[1][2 * nfp],     PA[1][kf], b0a, b1a);
                mma_f16(O[1][2 * nfp + 1], PA[1][kf], b0b, b1b);
            }
        }
        s ^= 1;
    }

    // ---- final l reduction + write fp16 ctx [B][S][H*64] ----
    #pragma unroll
    for (int st = 0; st < 2; st++) {
        float l0 = lsum[st][0], l1 = lsum[st][1];
        l0 += __shfl_xor_sync(0xffffffffu, l0, 1);
        l0 += __shfl_xor_sync(0xffffffffu, l0, 2);
        l1 += __shfl_xor_sync(0xffffffffu, l1, 1);
        l1 += __shfl_xor_sync(0xffffffffu, l1, 2);
        const float inv0 = 1.0f / l0, inv1 = 1.0f / l1;
        const size_t ob0 = ((size_t)b * SS + r0 + st * 16) * HID + (size_t)h * 64;
        const size_t ob1 = ob0 + (size_t)8 * HID;
        #pragma unroll
        for (int nf = 0; nf < 8; nf++) {
            *(__half2*)&g_ctxh[ob0 + nf * 8 + 2 * c] =
                __floats2half2_rn(O[st][nf][0] * inv0, O[st][nf][1] * inv0);
            *(__half2*)&g_ctxh[ob1 + nf * 8 + 2 * c] =
                __floats2half2_rn(O[st][nf][2] * inv1, O[st][nf][3] * inv1);
        }
    }
}

// ---------------------------------------------------------------------------
extern "C" void kernel_launch(void* const* d_in, const int* in_sizes, int n_in,
                              void* d_out, int out_size) {
    const float* x    = (const float*)d_in[0];
    const float* mask = (const float*)d_in[1];
    const float* Wq   = (const float*)d_in[2];
    const float* bq   = (const float*)d_in[3];
    const float* Wk   = (const float*)d_in[4];
    const float* bk   = (const float*)d_in[5];
    const float* Wv   = (const float*)d_in[6];
    const float* bv   = (const float*)d_in[7];
    const float* Wo   = (const float*)d_in[8];
    const float* bo   = (const float*)d_in[9];
    float* out = (float*)d_out;

    __half *p_xh, *p_wqkvh, *p_woh, *p_ctxh;
    float *p_qkv, *p_b2qkv, *p_b2o;
    __nv_bfloat16* p_maskb;
    cudaGetSymbolAddress((void**)&p_xh,     g_xh);
    cudaGetSymbolAddress((void**)&p_wqkvh,  g_wqkvh);
    cudaGetSymbolAddress((void**)&p_woh,    g_woh);
    cudaGetSymbolAddress((void**)&p_ctxh,   g_ctxh);
    cudaGetSymbolAddress((void**)&p_qkv,    g_qkv);
    cudaGetSymbolAddress((void**)&p_b2qkv,  g_b2qkv);
    cudaGetSymbolAddress((void**)&p_b2o,    g_b2o);
    cudaGetSymbolAddress((void**)&p_maskb,  g_maskb);

    // 0) single fused prep (all conversions + bias broadcast)
    prep<<<(PTOT / 4 + 255) / 256, 256>>>(x, mask, Wq, bq, Wk, bk, Wv, bv, Wo, bo);

    // 1) fused QKV projection (fp16 tensor cores, fp32 accumulate)
    gemm_h<<<dim3(NQKV / 128, MM / 128), 256>>>(p_xh, p_wqkvh, p_b2qkv, p_qkv,
                                                MM, NQKV, HID);

    // 2) rope + rmsnorm + relayout (fp16 outputs), V transpose
    rope_norm_q<<<SS, 512>>>();
    rope_norm_k<<<SS, 128>>>();
    transpose_v<<<dim3(SS / 128, BB * NKV), 256>>>();

    // 3) attention (4-warp register flash, fixed-max softmax)
    flash_attn_h16<<<dim3(SS / 128, BB * NH), 128>>>(p_maskb);

    // 4) output projection straight into d_out
    gemm_h<<<dim3(HID / 128, MM / 128), 256>>>(p_ctxh, p_woh, p_b2o, out,
                                               MM, HID, HID);
}